// round 1
// baseline (speedup 1.0000x reference)
#include <cuda_runtime.h>
#include <cuda_fp16.h>

#define NPTS 100000
#define CIN 96
#define CHID 576
#define COUT 96
#define KQ 24            // CIN / 4 (dp4a-packed k groups)
#define TM 32            // sites per block in fused kernel

// ---------------- device scratch (no cudaMalloc allowed) ----------------
__device__ __half g_x1[(size_t)NPTS * CHID];   // stage-1 activations, fp16 (exact)
__device__ int    g_featp[NPTS * KQ];          // feats packed int8x4
__device__ int    g_w1p[CHID * KQ];            // w1 transposed + packed int8x4

// ---------------- packing kernels ----------------
__global__ void pack_feats_kernel(const float* __restrict__ feats) {
    int idx = blockIdx.x * blockDim.x + threadIdx.x;
    if (idx >= NPTS * KQ) return;
    int site = idx / KQ, kq = idx % KQ;
    float4 f = *(const float4*)(feats + site * CIN + kq * 4);
    int a0 = (int)rintf(f.x), a1 = (int)rintf(f.y);
    int a2 = (int)rintf(f.z), a3 = (int)rintf(f.w);
    g_featp[idx] = (a0 & 0xFF) | ((a1 & 0xFF) << 8) | ((a2 & 0xFF) << 16) | ((a3 & 0xFF) << 24);
}

__global__ void pack_w1_kernel(const float* __restrict__ w1) {
    int idx = blockIdx.x * blockDim.x + threadIdx.x;
    if (idx >= CHID * KQ) return;
    int c = idx / KQ, kq = idx % KQ;
    const float* p = w1 + (kq * 4) * CHID + c;   // w1 is [CIN, CHID] row-major
    int a0 = (int)rintf(p[0]);
    int a1 = (int)rintf(p[CHID]);
    int a2 = (int)rintf(p[2 * CHID]);
    int a3 = (int)rintf(p[3 * CHID]);
    g_w1p[idx] = (a0 & 0xFF) | ((a1 & 0xFF) << 8) | ((a2 & 0xFF) << 16) | ((a3 & 0xFF) << 24);
}

// ---------------- stage 1: 1x1 expand conv (dp4a int8 GEMM) ----------------
// tile: 128 sites x 64 hid, 256 threads, each thread 8 sites x 4 hid
__global__ __launch_bounds__(256) void expand_kernel(
    const float* __restrict__ b1, const float* __restrict__ s1) {
    __shared__ int saT[KQ][132];   // [k][site], padded
    __shared__ int swp[KQ][64];    // [k][hid]
    int t = threadIdx.x;
    int site0 = blockIdx.x * 128;
    int c0 = blockIdx.y * 64;

    #pragma unroll
    for (int it = 0; it < 12; it++) {            // 128*24 = 3072 = 12*256
        int i = t + it * 256;
        int s = i / KQ, k = i % KQ;
        int site = site0 + s;
        saT[k][s] = (site < NPTS) ? g_featp[site * KQ + k] : 0;
    }
    #pragma unroll
    for (int it = 0; it < 6; it++) {             // 64*24 = 1536 = 6*256
        int i = t + it * 256;
        int c = i / KQ, k = i % KQ;
        swp[k][c] = g_w1p[(c0 + c) * KQ + k];
    }
    __syncthreads();

    int cq = (t & 15) * 4;
    int sg = (t >> 4) * 8;
    int acc[8][4];
    #pragma unroll
    for (int i = 0; i < 8; i++)
        #pragma unroll
        for (int j = 0; j < 4; j++) acc[i][j] = 0;

    #pragma unroll
    for (int k = 0; k < KQ; k++) {
        int4 a0 = *(const int4*)&saT[k][sg];
        int4 a1 = *(const int4*)&saT[k][sg + 4];
        int4 w  = *(const int4*)&swp[k][cq];
        int av[8] = {a0.x, a0.y, a0.z, a0.w, a1.x, a1.y, a1.z, a1.w};
        int wv[4] = {w.x, w.y, w.z, w.w};
        #pragma unroll
        for (int i = 0; i < 8; i++)
            #pragma unroll
            for (int j = 0; j < 4; j++)
                acc[i][j] = __dp4a(av[i], wv[j], acc[i][j]);
    }

    float rj[4], bj[4];
    #pragma unroll
    for (int j = 0; j < 4; j++) {
        rj[j] = rintf(s1[c0 + cq + j]) * (1.0f / 256.0f);
        bj[j] = b1[c0 + cq + j];
    }
    #pragma unroll
    for (int i = 0; i < 8; i++) {
        int site = site0 + sg + i;
        if (site < NPTS) {
            float v[4];
            #pragma unroll
            for (int j = 0; j < 4; j++) {
                float x = ((float)acc[i][j] + bj[j]) * rj[j];
                v[j] = fminf(fmaxf(x, 0.0f), 6.0f);   // clamp(+-128) then relu6 == clip(0,6)
            }
            __half2* dst = (__half2*)&g_x1[(size_t)site * CHID + c0 + cq];
            dst[0] = __floats2half2_rn(v[0], v[1]);
            dst[1] = __floats2half2_rn(v[2], v[3]);
        }
    }
}

// ---------------- stage 2+3: fused depthwise 3x3 + 1x1 project + residual ----------------
// one block handles TM=32 sites end-to-end; x2 lives only in SMEM.
#define SMEM2_BYTES (( (TM*CHID + CHID + CHID + 64*COUT) * 4 ) + (9*CHID * 2) + (9*TM * 4))

__global__ __launch_bounds__(256) void fused_kernel(
    const int* __restrict__ nbr,
    const float* __restrict__ w2, const float* __restrict__ b2,
    const float* __restrict__ w3, const float* __restrict__ b3,
    const float* __restrict__ s2, const float* __restrict__ s3,
    const float* __restrict__ s_main, const float* __restrict__ s_res,
    const float* __restrict__ feats,
    float* __restrict__ out) {
    extern __shared__ float smem[];
    float*  x2s  = smem;                        // TM*CHID fp32
    float*  sb2  = x2s + TM * CHID;             // CHID
    float*  sr2  = sb2 + CHID;                  // CHID
    float*  sw3  = sr2 + CHID;                  // 64*COUT (k-chunk of w3)
    __half* sw2  = (__half*)(sw3 + 64 * COUT);  // 9*CHID fp16 (exact: ints <=127)
    int*    snbr = (int*)(sw2 + 9 * CHID);      // 9*TM

    int t = threadIdx.x;
    int site0 = blockIdx.x * TM;

    for (int i = t; i < 9 * CHID; i += 256) sw2[i] = __float2half_rn(w2[i]);
    for (int i = t; i < CHID; i += 256) {
        sb2[i] = b2[i];
        sr2[i] = rintf(s2[i]) * (1.0f / 256.0f);
    }
    for (int i = t; i < 9 * TM; i += 256)
        snbr[i] = nbr[(i >> 5) * NPTS + site0 + (i & 31)];
    __syncthreads();

    // ---- Phase A: depthwise 3x3 sparse conv -> x2 tile in SMEM ----
    #pragma unroll 1
    for (int it = 0; it < 18; it++) {            // 32*144 quads = 18*256
        int q = t + it * 256;
        int site = q / 144;
        int cq = (q - site * 144) * 4;
        float a0 = sb2[cq], a1 = sb2[cq + 1], a2 = sb2[cq + 2], a3 = sb2[cq + 3];
        #pragma unroll
        for (int k = 0; k < 9; k++) {
            int j = snbr[k * TM + site];
            if (j >= 0) {
                uint2 raw = *(const uint2*)&g_x1[(size_t)j * CHID + cq];
                __half2 x01 = *(__half2*)&raw.x;
                __half2 x23 = *(__half2*)&raw.y;
                float2 f0 = __half22float2(x01);
                float2 f1 = __half22float2(x23);
                const __half2* wp = (const __half2*)&sw2[k * CHID + cq];
                float2 w0 = __half22float2(wp[0]);
                float2 w1v = __half22float2(wp[1]);
                a0 += f0.x * w0.x;  a1 += f0.y * w0.y;
                a2 += f1.x * w1v.x; a3 += f1.y * w1v.y;
            }
        }
        float4 r;
        r.x = fminf(fmaxf(a0 * sr2[cq + 0], 0.0f), 6.0f);
        r.y = fminf(fmaxf(a1 * sr2[cq + 1], 0.0f), 6.0f);
        r.z = fminf(fmaxf(a2 * sr2[cq + 2], 0.0f), 6.0f);
        r.w = fminf(fmaxf(a3 * sr2[cq + 3], 0.0f), 6.0f);
        *(float4*)&x2s[site * CHID + cq] = r;
    }
    __syncthreads();

    // ---- Phase B: project GEMM [32 x 576] @ [576 x 96] ----
    int colane = t & 31;     // cout lanes 0..31 (+32j)
    int sgrp = t >> 5;       // 8 site groups of 4
    float acc[4][3];
    #pragma unroll
    for (int i = 0; i < 4; i++)
        #pragma unroll
        for (int j = 0; j < 3; j++) acc[i][j] = 0.0f;

    for (int kc = 0; kc < CHID; kc += 64) {
        __syncthreads();
        #pragma unroll
        for (int it = 0; it < 24; it++) {        // 64*96 = 6144 = 24*256
            int i = t + it * 256;
            sw3[i] = w3[(kc + i / COUT) * COUT + (i % COUT)];
        }
        __syncthreads();
        #pragma unroll 4
        for (int kk = 0; kk < 64; kk += 4) {
            float4 xq[4];
            #pragma unroll
            for (int i = 0; i < 4; i++)
                xq[i] = *(const float4*)&x2s[(sgrp * 4 + i) * CHID + kc + kk];
            #pragma unroll
            for (int d = 0; d < 4; d++) {
                float wv[3];
                #pragma unroll
                for (int j = 0; j < 3; j++)
                    wv[j] = sw3[(kk + d) * COUT + colane + 32 * j];
                #pragma unroll
                for (int i = 0; i < 4; i++) {
                    float xv = (d == 0) ? xq[i].x : (d == 1) ? xq[i].y
                             : (d == 2) ? xq[i].z : xq[i].w;
                    acc[i][0] += xv * wv[0];
                    acc[i][1] += xv * wv[1];
                    acc[i][2] += xv * wv[2];
                }
            }
        }
    }

    // ---- epilogue: requant + clamp + scaled residual ----
    float smain = rintf(s_main[0]) * 256.0f;
    float sres  = rintf(s_res[0]) * 256.0f;
    #pragma unroll
    for (int i = 0; i < 4; i++) {
        int site = site0 + sgrp * 4 + i;
        #pragma unroll
        for (int j = 0; j < 3; j++) {
            int co = colane + 32 * j;
            float r3 = rintf(s3[co]) * (1.0f / 256.0f);
            float v = (acc[i][j] + b3[co]) * r3;
            v = fminf(fmaxf(v, -128.0f), 128.0f);
            out[(size_t)site * COUT + co] = smain * v + sres * feats[(size_t)site * CIN + co];
        }
    }
}

// ---------------- launch ----------------
extern "C" void kernel_launch(void* const* d_in, const int* in_sizes, int n_in,
                              void* d_out, int out_size) {
    const float* feats = (const float*)d_in[0];
    const int*   nbr   = (const int*)d_in[1];
    const float* w1    = (const float*)d_in[2];
    const float* b1    = (const float*)d_in[3];
    const float* w2    = (const float*)d_in[4];
    const float* b2    = (const float*)d_in[5];
    const float* w3    = (const float*)d_in[6];
    const float* b3    = (const float*)d_in[7];
    const float* s1    = (const float*)d_in[8];
    const float* s2    = (const float*)d_in[9];
    const float* s3    = (const float*)d_in[10];
    const float* sm_   = (const float*)d_in[11];
    const float* sr_   = (const float*)d_in[12];
    float* out = (float*)d_out;

    cudaFuncSetAttribute(fused_kernel, cudaFuncAttributeMaxDynamicSharedMemorySize, SMEM2_BYTES);

    pack_feats_kernel<<<(NPTS * KQ + 255) / 256, 256>>>(feats);
    pack_w1_kernel<<<(CHID * KQ + 255) / 256, 256>>>(w1);
    expand_kernel<<<dim3((NPTS + 127) / 128, CHID / 64), 256>>>(b1, s1);
    fused_kernel<<<NPTS / TM, 256, SMEM2_BYTES>>>(nbr, w2, b2, w3, b3, s2, s3, sm_, sr_, feats, out);
}

// round 2
// speedup vs baseline: 1.5968x; 1.5968x over previous
#include <cuda_runtime.h>
#include <cuda_fp16.h>
#include <cstdint>

#define NPTS 100000
#define CIN  96
#define CHID 576
#define COUT 96
#define TM   64           // sites per block
#define LDX  584          // x2s shared stride (halves): 1168B % 128 == 16 -> ldmatrix conflict-free
#define FS   120          // feats tile shared stride (halves): 240B % 128 == 112 -> conflict-free
#define NBLK ((NPTS + TM - 1) / TM)   // 1563

// ---------------- device scratch ----------------
__device__ __half g_x1[(size_t)NPTS * CHID];      // stage-1 activations (fp16)
__device__ __half g_featsh[(size_t)NPTS * CIN];   // feats as fp16 (exact)
__device__ uint2  g_w1f[6  * 72 * 32];            // w1 B-fragments [ka][na][lane]
__device__ uint2  g_w3f[36 * 12 * 32];            // w3 B-fragments [ka][na][lane]

// ---------------- mma helpers ----------------
__device__ __forceinline__ void ldmatrix_x4(uint32_t* r, uint32_t saddr) {
    asm volatile("ldmatrix.sync.aligned.m8n8.x4.shared.b16 {%0,%1,%2,%3}, [%4];"
                 : "=r"(r[0]), "=r"(r[1]), "=r"(r[2]), "=r"(r[3]) : "r"(saddr));
}
__device__ __forceinline__ void mma16816(float* c, const uint32_t* a, const uint32_t* b) {
    asm volatile("mma.sync.aligned.m16n8k16.row.col.f32.f16.f16.f32 "
                 "{%0,%1,%2,%3}, {%4,%5,%6,%7}, {%8,%9}, {%0,%1,%2,%3};"
                 : "+f"(c[0]), "+f"(c[1]), "+f"(c[2]), "+f"(c[3])
                 : "r"(a[0]), "r"(a[1]), "r"(a[2]), "r"(a[3]), "r"(b[0]), "r"(b[1]));
}
__device__ __forceinline__ uint32_t pack2(float lo, float hi) {
    __half2 h = __floats2half2_rn(lo, hi);
    return *(uint32_t*)&h;
}

// ---------------- pack kernels ----------------
__global__ void pack_feats_h(const float* __restrict__ feats) {
    int i = blockIdx.x * blockDim.x + threadIdx.x;          // half2 index
    if (i >= NPTS * CIN / 2) return;
    float2 f = *(const float2*)(feats + 2 * i);
    *(uint32_t*)&g_featsh[2 * i] = pack2(f.x, f.y);
}
// w1 [96][576] row-major -> B fragments, B[k][n] = w1[k][n]
__global__ void pack_w1f(const float* __restrict__ w1) {
    int idx = blockIdx.x * blockDim.x + threadIdx.x;
    if (idx >= 6 * 72 * 32) return;
    int lane = idx & 31, na = (idx >> 5) % 72, ka = idx / (32 * 72);
    int k0 = ka * 16 + (lane & 3) * 2;
    int n  = na * 8 + (lane >> 2);
    uint2 v;
    v.x = pack2(w1[k0 * CHID + n],       w1[(k0 + 1) * CHID + n]);
    v.y = pack2(w1[(k0 + 8) * CHID + n], w1[(k0 + 9) * CHID + n]);
    g_w1f[idx] = v;
}
// w3 [576][96] row-major -> B fragments
__global__ void pack_w3f(const float* __restrict__ w3) {
    int idx = blockIdx.x * blockDim.x + threadIdx.x;
    if (idx >= 36 * 12 * 32) return;
    int lane = idx & 31, na = (idx >> 5) % 12, ka = idx / (32 * 12);
    int k0 = ka * 16 + (lane & 3) * 2;
    int n  = na * 8 + (lane >> 2);
    uint2 v;
    v.x = pack2(w3[k0 * COUT + n],       w3[(k0 + 1) * COUT + n]);
    v.y = pack2(w3[(k0 + 8) * COUT + n], w3[(k0 + 9) * COUT + n]);
    g_w3f[idx] = v;
}

// ---------------- stage 1: 1x1 expand (HMMA, bit-exact) ----------------
// grid (NBLK, 6): 64 sites x 96 hid-cols per block. 256 thr = 8 warps.
__global__ __launch_bounds__(256) void expand_kernel(
    const float* __restrict__ b1, const float* __restrict__ s1) {
    __shared__ __align__(16) __half sfeat[TM * FS];
    int t = threadIdx.x;
    int site0 = blockIdx.x * TM;
    int nchunk = blockIdx.y;      // 0..5, 96 cols each

    // load feats tile [64][96] fp16 (zeros for tail sites)
    #pragma unroll
    for (int it = 0; it < 12; it++) {                 // 64*48 half2 = 3072
        int i = t + it * 256;
        int s = i / 48, c2 = i - s * 48;
        uint32_t v = 0;
        if (site0 + s < NPTS) v = *(const uint32_t*)&g_featsh[(size_t)(site0 + s) * CIN + c2 * 2];
        *(uint32_t*)&sfeat[s * FS + c2 * 2] = v;
    }
    __syncthreads();

    int warp = t >> 5, lane = t & 31;
    int mbase = (warp & 1) * 32;          // rows 0-31 / 32-63
    int natom0 = (warp >> 1) * 3;         // block-local n-atoms (of 12)
    uint32_t sbase = (uint32_t)__cvta_generic_to_shared(sfeat);

    float acc[2][3][4];
    #pragma unroll
    for (int mi = 0; mi < 2; mi++)
        #pragma unroll
        for (int ni = 0; ni < 3; ni++)
            #pragma unroll
            for (int j = 0; j < 4; j++) acc[mi][ni][j] = 0.0f;

    #pragma unroll
    for (int ka = 0; ka < 6; ka++) {
        uint32_t a[2][4];
        #pragma unroll
        for (int mi = 0; mi < 2; mi++) {
            int row = mbase + mi * 16 + (lane & 15);
            uint32_t addr = sbase + (row * FS + ka * 16 + (lane >> 4) * 8) * 2;
            ldmatrix_x4(a[mi], addr);
        }
        uint2 b[3];
        #pragma unroll
        for (int ni = 0; ni < 3; ni++)
            b[ni] = g_w1f[(ka * 72 + nchunk * 12 + natom0 + ni) * 32 + lane];
        #pragma unroll
        for (int mi = 0; mi < 2; mi++)
            #pragma unroll
            for (int ni = 0; ni < 3; ni++)
                mma16816(acc[mi][ni], a[mi], (const uint32_t*)&b[ni]);
    }

    // epilogue: requant + relu6 -> g_x1 fp16
    int r = lane >> 2, cl = (lane & 3) * 2;
    #pragma unroll
    for (int ni = 0; ni < 3; ni++) {
        int ch = nchunk * 96 + natom0 * 8 + ni * 8 + cl;   // global hid channel
        float rs0 = rintf(s1[ch]) * (1.0f / 256.0f);
        float rs1 = rintf(s1[ch + 1]) * (1.0f / 256.0f);
        float bb0 = b1[ch], bb1 = b1[ch + 1];
        #pragma unroll
        for (int mi = 0; mi < 2; mi++) {
            #pragma unroll
            for (int half = 0; half < 2; half++) {
                int site = site0 + mbase + mi * 16 + r + half * 8;
                if (site < NPTS) {
                    float v0 = fminf(fmaxf((acc[mi][ni][half * 2 + 0] + bb0) * rs0, 0.0f), 6.0f);
                    float v1 = fminf(fmaxf((acc[mi][ni][half * 2 + 1] + bb1) * rs1, 0.0f), 6.0f);
                    *(uint32_t*)&g_x1[(size_t)site * CHID + ch] = pack2(v0, v1);
                }
            }
        }
    }
}

// ---------------- stage 2+3: fused depthwise + project (HMMA) + residual ----------------
#define SMEM_F ((TM * LDX + 9 * CHID) * 2 + (CHID * 2 + 9 * TM) * 4)   // 92032 B

__global__ __launch_bounds__(256) void fused_kernel(
    const int* __restrict__ nbr,
    const float* __restrict__ w2, const float* __restrict__ b2,
    const float* __restrict__ b3,
    const float* __restrict__ s2, const float* __restrict__ s3,
    const float* __restrict__ s_main, const float* __restrict__ s_res,
    const float* __restrict__ feats,
    float* __restrict__ out) {
    extern __shared__ __align__(16) char smraw[];
    __half* x2s  = (__half*)smraw;                 // [64][584]
    __half* sw2  = x2s + TM * LDX;                 // [9][576]
    float*  sb2  = (float*)(sw2 + 9 * CHID);       // [576]
    float*  sr2  = sb2 + CHID;                     // [576]
    int*    snbr = (int*)(sr2 + CHID);             // [9][64]

    int t = threadIdx.x;
    int site0 = blockIdx.x * TM;
    int nsite = NPTS - site0; if (nsite > TM) nsite = TM;

    for (int i = t; i < 9 * CHID / 2; i += 256) {
        float2 wv = *(const float2*)(w2 + 2 * i);
        *(uint32_t*)&sw2[2 * i] = pack2(wv.x, wv.y);
    }
    for (int i = t; i < CHID; i += 256) {
        sb2[i] = b2[i];
        sr2[i] = rintf(s2[i]) * (1.0f / 256.0f);
    }
    for (int i = t; i < 9 * TM; i += 256) {
        int s = i & (TM - 1);
        snbr[i] = (s < nsite) ? nbr[(i / TM) * NPTS + site0 + s] : -1;
    }
    __syncthreads();

    // ---- Phase A: depthwise 3x3 gather -> x2 tile (fp16) in SMEM ----
    #pragma unroll 1
    for (int it = 0; it < 36; it++) {              // 64*144 quad-tasks
        int q = t + it * 256;
        int site = q / 144;
        int cq = (q - site * 144) * 4;
        float r0 = 0.f, r1 = 0.f, r2v = 0.f, r3v = 0.f;
        if (site < nsite) {
            float a0 = sb2[cq], a1 = sb2[cq + 1], a2 = sb2[cq + 2], a3 = sb2[cq + 3];
            #pragma unroll
            for (int k = 0; k < 9; k++) {
                int j = snbr[k * TM + site];
                if (j >= 0) {
                    uint2 raw = *(const uint2*)&g_x1[(size_t)j * CHID + cq];
                    float2 f0 = __half22float2(*(__half2*)&raw.x);
                    float2 f1 = __half22float2(*(__half2*)&raw.y);
                    uint2 wr = *(const uint2*)&sw2[k * CHID + cq];
                    float2 w0 = __half22float2(*(__half2*)&wr.x);
                    float2 w1v = __half22float2(*(__half2*)&wr.y);
                    a0 += f0.x * w0.x;  a1 += f0.y * w0.y;
                    a2 += f1.x * w1v.x; a3 += f1.y * w1v.y;
                }
            }
            r0  = fminf(fmaxf(a0 * sr2[cq + 0], 0.f), 6.f);
            r1  = fminf(fmaxf(a1 * sr2[cq + 1], 0.f), 6.f);
            r2v = fminf(fmaxf(a2 * sr2[cq + 2], 0.f), 6.f);
            r3v = fminf(fmaxf(a3 * sr2[cq + 3], 0.f), 6.f);
        }
        *(uint32_t*)&x2s[site * LDX + cq]     = pack2(r0, r1);
        *(uint32_t*)&x2s[site * LDX + cq + 2] = pack2(r2v, r3v);
    }
    __syncthreads();

    // ---- Phase B: project GEMM [64 x 576] @ [576 x 96] via HMMA ----
    int warp = t >> 5, lane = t & 31;
    int mbase = (warp & 1) * 32;
    int natom0 = (warp >> 1) * 3;
    uint32_t sbase = (uint32_t)__cvta_generic_to_shared(x2s);

    float acc[2][3][4];
    #pragma unroll
    for (int mi = 0; mi < 2; mi++)
        #pragma unroll
        for (int ni = 0; ni < 3; ni++)
            #pragma unroll
            for (int j = 0; j < 4; j++) acc[mi][ni][j] = 0.0f;

    #pragma unroll 2
    for (int ka = 0; ka < 36; ka++) {
        uint32_t a[2][4];
        #pragma unroll
        for (int mi = 0; mi < 2; mi++) {
            int row = mbase + mi * 16 + (lane & 15);
            uint32_t addr = sbase + (row * LDX + ka * 16 + (lane >> 4) * 8) * 2;
            ldmatrix_x4(a[mi], addr);
        }
        uint2 b[3];
        #pragma unroll
        for (int ni = 0; ni < 3; ni++)
            b[ni] = g_w3f[(ka * 12 + natom0 + ni) * 32 + lane];
        #pragma unroll
        for (int mi = 0; mi < 2; mi++)
            #pragma unroll
            for (int ni = 0; ni < 3; ni++)
                mma16816(acc[mi][ni], a[mi], (const uint32_t*)&b[ni]);
    }

    // ---- epilogue: requant + clamp + scaled residual ----
    float smain = rintf(s_main[0]) * 256.0f;
    float sres  = rintf(s_res[0]) * 256.0f;
    int r = lane >> 2, cl = (lane & 3) * 2;
    #pragma unroll
    for (int ni = 0; ni < 3; ni++) {
        int co = natom0 * 8 + ni * 8 + cl;
        float rs0 = rintf(s3[co]) * (1.0f / 256.0f);
        float rs1 = rintf(s3[co + 1]) * (1.0f / 256.0f);
        float bb0 = b3[co], bb1 = b3[co + 1];
        #pragma unroll
        for (int mi = 0; mi < 2; mi++) {
            #pragma unroll
            for (int half = 0; half < 2; half++) {
                int site = site0 + mbase + mi * 16 + r + half * 8;
                if (site < NPTS) {
                    float v0 = (acc[mi][ni][half * 2 + 0] + bb0) * rs0;
                    float v1 = (acc[mi][ni][half * 2 + 1] + bb1) * rs1;
                    v0 = fminf(fmaxf(v0, -128.0f), 128.0f);
                    v1 = fminf(fmaxf(v1, -128.0f), 128.0f);
                    float2 fr = *(const float2*)(feats + (size_t)site * CIN + co);
                    float2 o;
                    o.x = smain * v0 + sres * fr.x;
                    o.y = smain * v1 + sres * fr.y;
                    *(float2*)(out + (size_t)site * COUT + co) = o;
                }
            }
        }
    }
}

// ---------------- launch ----------------
extern "C" void kernel_launch(void* const* d_in, const int* in_sizes, int n_in,
                              void* d_out, int out_size) {
    const float* feats = (const float*)d_in[0];
    const int*   nbr   = (const int*)d_in[1];
    const float* w1    = (const float*)d_in[2];
    const float* b1    = (const float*)d_in[3];
    const float* w2    = (const float*)d_in[4];
    const float* b2    = (const float*)d_in[5];
    const float* w3    = (const float*)d_in[6];
    const float* b3    = (const float*)d_in[7];
    const float* s1    = (const float*)d_in[8];
    const float* s2    = (const float*)d_in[9];
    const float* s3    = (const float*)d_in[10];
    const float* sm_   = (const float*)d_in[11];
    const float* sr_   = (const float*)d_in[12];
    float* out = (float*)d_out;

    cudaFuncSetAttribute(fused_kernel, cudaFuncAttributeMaxDynamicSharedMemorySize, SMEM_F);

    pack_feats_h<<<(NPTS * CIN / 2 + 255) / 256, 256>>>(feats);
    pack_w1f<<<(6 * 72 * 32 + 255) / 256, 256>>>(w1);
    pack_w3f<<<(36 * 12 * 32 + 255) / 256, 256>>>(w3);
    expand_kernel<<<dim3(NBLK, 6), 256>>>(b1, s1);
    fused_kernel<<<NBLK, 256, SMEM_F>>>(nbr, w2, b2, b3, s2, s3, sm_, sr_, feats, out);
}

// round 3
// speedup vs baseline: 2.1218x; 1.3288x over previous
#include <cuda_runtime.h>
#include <cuda_fp16.h>
#include <cstdint>

#define NPTS 100000
#define CIN  96
#define CHID 576
#define COUT 96
#define TM   64
#define LDX  584          // x2s stride (halves): 1168B row -> ldmatrix conflict-free
#define FS   120          // feats tile stride (halves)
#define XS   104          // expand output staging stride (halves), 208B 16B-aligned
#define NBLK ((NPTS + TM - 1) / TM)   // 1563

// ---------------- device scratch ----------------
__device__ __half g_x1[(size_t)NPTS * CHID];      // stage-1 activations (fp16, exact)
__device__ uint2  g_w1f[6  * 72 * 32];            // w1 B-fragments [ka][na][lane]
__device__ uint2  g_w3f[36 * 12 * 32];            // w3 B-fragments [ka][na][lane]

// ---------------- helpers ----------------
__device__ __forceinline__ void ldmatrix_x4(uint32_t* r, uint32_t saddr) {
    asm volatile("ldmatrix.sync.aligned.m8n8.x4.shared.b16 {%0,%1,%2,%3}, [%4];"
                 : "=r"(r[0]), "=r"(r[1]), "=r"(r[2]), "=r"(r[3]) : "r"(saddr));
}
__device__ __forceinline__ void mma16816(float* c, const uint32_t* a, const uint32_t* b) {
    asm volatile("mma.sync.aligned.m16n8k16.row.col.f32.f16.f16.f32 "
                 "{%0,%1,%2,%3}, {%4,%5,%6,%7}, {%8,%9}, {%0,%1,%2,%3};"
                 : "+f"(c[0]), "+f"(c[1]), "+f"(c[2]), "+f"(c[3])
                 : "r"(a[0]), "r"(a[1]), "r"(a[2]), "r"(a[3]), "r"(b[0]), "r"(b[1]));
}
__device__ __forceinline__ uint32_t pack2(float lo, float hi) {
    __half2 h = __floats2half2_rn(lo, hi);
    return *(uint32_t*)&h;
}
// packed f32x2 ops (Blackwell)
__device__ __forceinline__ unsigned long long pk64(float lo, float hi) {
    unsigned long long v;
    asm("mov.b64 %0, {%1, %2};" : "=l"(v) : "f"(lo), "f"(hi));
    return v;
}
__device__ __forceinline__ void upk64(float& lo, float& hi, unsigned long long v) {
    asm("mov.b64 {%0, %1}, %2;" : "=f"(lo), "=f"(hi) : "l"(v));
}
__device__ __forceinline__ void ffma2(unsigned long long& acc, unsigned long long a, unsigned long long b) {
    asm("fma.rn.f32x2 %0, %1, %2, %0;" : "+l"(acc) : "l"(a), "l"(b));
}
__device__ __forceinline__ unsigned long long fmul2(unsigned long long a, unsigned long long b) {
    unsigned long long o;
    asm("mul.rn.f32x2 %0, %1, %2;" : "=l"(o) : "l"(a), "l"(b));
    return o;
}
__device__ __forceinline__ unsigned long long h2tof2(uint32_t h) {
    float2 f = __half22float2(*(__half2*)&h);
    return pk64(f.x, f.y);
}

// ---------------- pack kernels ----------------
__global__ void pack_w1f(const float* __restrict__ w1) {
    int idx = blockIdx.x * blockDim.x + threadIdx.x;
    if (idx >= 6 * 72 * 32) return;
    int lane = idx & 31, na = (idx >> 5) % 72, ka = idx / (32 * 72);
    int k0 = ka * 16 + (lane & 3) * 2;
    int n  = na * 8 + (lane >> 2);
    uint2 v;
    v.x = pack2(w1[k0 * CHID + n],       w1[(k0 + 1) * CHID + n]);
    v.y = pack2(w1[(k0 + 8) * CHID + n], w1[(k0 + 9) * CHID + n]);
    g_w1f[idx] = v;
}
__global__ void pack_w3f(const float* __restrict__ w3) {
    int idx = blockIdx.x * blockDim.x + threadIdx.x;
    if (idx >= 36 * 12 * 32) return;
    int lane = idx & 31, na = (idx >> 5) % 12, ka = idx / (32 * 12);
    int k0 = ka * 16 + (lane & 3) * 2;
    int n  = na * 8 + (lane >> 2);
    uint2 v;
    v.x = pack2(w3[k0 * COUT + n],       w3[(k0 + 1) * COUT + n]);
    v.y = pack2(w3[(k0 + 8) * COUT + n], w3[(k0 + 9) * COUT + n]);
    g_w3f[idx] = v;
}

// ---------------- stage 1: 1x1 expand (HMMA, bit-exact), single pass ----------------
__global__ __launch_bounds__(256) void expand_kernel(
    const float* __restrict__ feats,
    const float* __restrict__ b1, const float* __restrict__ s1) {
    __shared__ __align__(16) __half sfeat[TM * FS];
    __shared__ __align__(16) __half sxout[TM * XS];
    __shared__ float sb1[CHID], ss1[CHID];
    int t = threadIdx.x;
    int site0 = blockIdx.x * TM;

    #pragma unroll
    for (int it = 0; it < 12; it++) {                 // 64*48 half2
        int i = t + it * 256;
        int s = i / 48, c2 = i - s * 48;
        uint32_t v = 0;
        if (site0 + s < NPTS) {
            float2 f = *(const float2*)(feats + (size_t)(site0 + s) * CIN + 2 * c2);
            v = pack2(f.x, f.y);
        }
        *(uint32_t*)&sfeat[s * FS + 2 * c2] = v;
    }
    for (int i = t; i < CHID; i += 256) {
        sb1[i] = b1[i];
        ss1[i] = rintf(s1[i]) * (1.0f / 256.0f);
    }
    __syncthreads();

    int warp = t >> 5, lane = t & 31;
    int mbase = (warp & 1) * 32;
    int natom0 = (warp >> 1) * 3;
    uint32_t sbase = (uint32_t)__cvta_generic_to_shared(sfeat);

    // A fragments once, reused across 6 chunks
    uint32_t a[6][2][4];
    #pragma unroll
    for (int ka = 0; ka < 6; ka++)
        #pragma unroll
        for (int mi = 0; mi < 2; mi++) {
            int row = mbase + mi * 16 + (lane & 15);
            ldmatrix_x4(a[ka][mi], sbase + (row * FS + ka * 16 + (lane >> 4) * 8) * 2);
        }

    int r = lane >> 2, cl = (lane & 3) * 2;
    for (int c = 0; c < 6; c++) {
        float acc[2][3][4];
        #pragma unroll
        for (int mi = 0; mi < 2; mi++)
            #pragma unroll
            for (int ni = 0; ni < 3; ni++)
                #pragma unroll
                for (int j = 0; j < 4; j++) acc[mi][ni][j] = 0.0f;
        #pragma unroll
        for (int ka = 0; ka < 6; ka++) {
            uint2 b[3];
            #pragma unroll
            for (int ni = 0; ni < 3; ni++)
                b[ni] = g_w1f[(ka * 72 + c * 12 + natom0 + ni) * 32 + lane];
            #pragma unroll
            for (int mi = 0; mi < 2; mi++)
                #pragma unroll
                for (int ni = 0; ni < 3; ni++)
                    mma16816(acc[mi][ni], a[ka][mi], (const uint32_t*)&b[ni]);
        }
        // epilogue -> staging smem
        #pragma unroll
        for (int ni = 0; ni < 3; ni++) {
            int chl = natom0 * 8 + ni * 8 + cl;       // 0..95 within chunk
            int ch = c * 96 + chl;
            float rs0 = ss1[ch], rs1 = ss1[ch + 1];
            float bb0 = sb1[ch], bb1 = sb1[ch + 1];
            #pragma unroll
            for (int mi = 0; mi < 2; mi++)
                #pragma unroll
                for (int half = 0; half < 2; half++) {
                    int row = mbase + mi * 16 + r + half * 8;
                    float v0 = fminf(fmaxf((acc[mi][ni][half * 2 + 0] + bb0) * rs0, 0.0f), 6.0f);
                    float v1 = fminf(fmaxf((acc[mi][ni][half * 2 + 1] + bb1) * rs1, 0.0f), 6.0f);
                    *(uint32_t*)&sxout[row * XS + chl] = pack2(v0, v1);
                }
        }
        __syncthreads();
        // coalesced write: 64 rows x 192B, 16B lanes
        #pragma unroll
        for (int it = 0; it < 3; it++) {
            int i = t + it * 256;
            int row = i / 12, q = i - row * 12;
            if (site0 + row < NPTS) {
                uint4 v = *(uint4*)&sxout[row * XS + q * 8];
                *(uint4*)&g_x1[(size_t)(site0 + row) * CHID + c * 96 + q * 8] = v;
            }
        }
        __syncthreads();
    }
}

// ---------------- stage 2+3: fused depthwise + project (HMMA) + residual ----------------
#define SMEM_F ((TM * LDX + 9 * CHID) * 2 + (2 * CHID + TM * 12) * 4)   // 92800 B

__global__ __launch_bounds__(288, 2) void fused_kernel(
    const int* __restrict__ nbr,
    const float* __restrict__ w2, const float* __restrict__ b2,
    const float* __restrict__ b3,
    const float* __restrict__ s2, const float* __restrict__ s3,
    const float* __restrict__ s_main, const float* __restrict__ s_res,
    const float* __restrict__ feats,
    float* __restrict__ out) {
    extern __shared__ __align__(16) char smraw[];
    __half* x2s   = (__half*)smraw;                 // [64][584]
    __half* sw2   = x2s + TM * LDX;                 // [9][576]
    float*  sb2   = (float*)(sw2 + 9 * CHID);       // [576]
    float*  sr2   = sb2 + CHID;                     // [576]
    int*    snbrp = (int*)(sr2 + CHID);             // [64][12] site-major, padded

    int t = threadIdx.x;
    int site0 = blockIdx.x * TM;
    int nsite = NPTS - site0; if (nsite > TM) nsite = TM;

    for (int i = t; i < 9 * CHID / 2; i += 288) {
        float2 wv = *(const float2*)(w2 + 2 * i);
        *(uint32_t*)&sw2[2 * i] = pack2(wv.x, wv.y);
    }
    for (int i = t; i < CHID; i += 288) {
        sb2[i] = b2[i];
        sr2[i] = rintf(s2[i]) * (1.0f / 256.0f);
    }
    for (int i = t; i < TM * 12; i += 288) {
        int k = i / TM, s = i - k * TM;              // coalesced over s per k
        int v = -1;
        if (k < 9 && s < nsite) v = nbr[k * NPTS + site0 + s];
        snbrp[s * 12 + k] = v;
    }
    __syncthreads();

    // ---- Phase A: depthwise 3x3 gather, thread = fixed 4 channels, 32 sites ----
    {
        int g = t % 144, shalf = t / 144;
        int cq = g * 4;
        const __half* x1cq = g_x1 + cq;

        unsigned long long w01[9], w23[9];
        #pragma unroll
        for (int k = 0; k < 9; k++) {
            uint2 wr = *(const uint2*)&sw2[k * CHID + cq];
            w01[k] = h2tof2(wr.x);
            w23[k] = h2tof2(wr.y);
        }
        unsigned long long b01 = pk64(sb2[cq], sb2[cq + 1]);
        unsigned long long b23 = pk64(sb2[cq + 2], sb2[cq + 3]);
        unsigned long long r01 = pk64(sr2[cq], sr2[cq + 1]);
        unsigned long long r23 = pk64(sr2[cq + 2], sr2[cq + 3]);

        #pragma unroll 1
        for (int s = 0; s < 32; s++) {
            int site = shalf * 32 + s;
            int4 na = *(const int4*)&snbrp[site * 12];
            int4 nb = *(const int4*)&snbrp[site * 12 + 4];
            int  n8 = snbrp[site * 12 + 8];
            unsigned long long a01 = b01, a23 = b23;
            #define TAP(J, K) do { int _j = (J); if (_j >= 0) { \
                uint2 v = *(const uint2*)(x1cq + (size_t)_j * CHID); \
                ffma2(a01, h2tof2(v.x), w01[K]); \
                ffma2(a23, h2tof2(v.y), w23[K]); } } while (0)
            TAP(na.x, 0); TAP(na.y, 1); TAP(na.z, 2); TAP(na.w, 3);
            TAP(nb.x, 4); TAP(nb.y, 5); TAP(nb.z, 6); TAP(nb.w, 7);
            TAP(n8, 8);
            #undef TAP
            a01 = fmul2(a01, r01);
            a23 = fmul2(a23, r23);
            float v0, v1, v2, v3;
            upk64(v0, v1, a01); upk64(v2, v3, a23);
            v0 = fminf(fmaxf(v0, 0.f), 6.f); v1 = fminf(fmaxf(v1, 0.f), 6.f);
            v2 = fminf(fmaxf(v2, 0.f), 6.f); v3 = fminf(fmaxf(v3, 0.f), 6.f);
            uint2 pr; pr.x = pack2(v0, v1); pr.y = pack2(v2, v3);
            *(uint2*)&x2s[site * LDX + cq] = pr;
        }
    }
    __syncthreads();

    // ---- Phase B: project GEMM [64x576]@[576x96] via HMMA (warps 0..7) ----
    int warp = t >> 5, lane = t & 31;
    if (warp < 8) {
        int mbase = (warp & 1) * 32;
        int natom0 = (warp >> 1) * 3;
        uint32_t sbase = (uint32_t)__cvta_generic_to_shared(x2s);

        float acc[2][3][4];
        #pragma unroll
        for (int mi = 0; mi < 2; mi++)
            #pragma unroll
            for (int ni = 0; ni < 3; ni++)
                #pragma unroll
                for (int j = 0; j < 4; j++) acc[mi][ni][j] = 0.0f;

        #pragma unroll 2
        for (int ka = 0; ka < 36; ka++) {
            uint32_t a[2][4];
            #pragma unroll
            for (int mi = 0; mi < 2; mi++) {
                int row = mbase + mi * 16 + (lane & 15);
                ldmatrix_x4(a[mi], sbase + (row * LDX + ka * 16 + (lane >> 4) * 8) * 2);
            }
            uint2 b[3];
            #pragma unroll
            for (int ni = 0; ni < 3; ni++)
                b[ni] = g_w3f[(ka * 12 + natom0 + ni) * 32 + lane];
            #pragma unroll
            for (int mi = 0; mi < 2; mi++)
                #pragma unroll
                for (int ni = 0; ni < 3; ni++)
                    mma16816(acc[mi][ni], a[mi], (const uint32_t*)&b[ni]);
        }

        // epilogue: requant + clamp + scaled residual
        float smain = rintf(s_main[0]) * 256.0f;
        float sres  = rintf(s_res[0]) * 256.0f;
        int r = lane >> 2, cl = (lane & 3) * 2;
        #pragma unroll
        for (int ni = 0; ni < 3; ni++) {
            int co = natom0 * 8 + ni * 8 + cl;
            float rs0 = rintf(s3[co]) * (1.0f / 256.0f);
            float rs1 = rintf(s3[co + 1]) * (1.0f / 256.0f);
            float bb0 = b3[co], bb1 = b3[co + 1];
            #pragma unroll
            for (int mi = 0; mi < 2; mi++)
                #pragma unroll
                for (int half = 0; half < 2; half++) {
                    int site = site0 + mbase + mi * 16 + r + half * 8;
                    if (site < NPTS) {
                        float v0 = (acc[mi][ni][half * 2 + 0] + bb0) * rs0;
                        float v1 = (acc[mi][ni][half * 2 + 1] + bb1) * rs1;
                        v0 = fminf(fmaxf(v0, -128.0f), 128.0f);
                        v1 = fminf(fmaxf(v1, -128.0f), 128.0f);
                        float2 fr = *(const float2*)(feats + (size_t)site * CIN + co);
                        float2 o;
                        o.x = smain * v0 + sres * fr.x;
                        o.y = smain * v1 + sres * fr.y;
                        *(float2*)(out + (size_t)site * COUT + co) = o;
                    }
                }
        }
    }
}

// ---------------- launch ----------------
extern "C" void kernel_launch(void* const* d_in, const int* in_sizes, int n_in,
                              void* d_out, int out_size) {
    const float* feats = (const float*)d_in[0];
    const int*   nbr   = (const int*)d_in[1];
    const float* w1    = (const float*)d_in[2];
    const float* b1    = (const float*)d_in[3];
    const float* w2    = (const float*)d_in[4];
    const float* b2    = (const float*)d_in[5];
    const float* w3    = (const float*)d_in[6];
    const float* b3    = (const float*)d_in[7];
    const float* s1    = (const float*)d_in[8];
    const float* s2    = (const float*)d_in[9];
    const float* s3    = (const float*)d_in[10];
    const float* sm_   = (const float*)d_in[11];
    const float* sr_   = (const float*)d_in[12];
    float* out = (float*)d_out;

    cudaFuncSetAttribute(fused_kernel, cudaFuncAttributeMaxDynamicSharedMemorySize, SMEM_F);

    pack_w1f<<<(6 * 72 * 32 + 255) / 256, 256>>>(w1);
    pack_w3f<<<(36 * 12 * 32 + 255) / 256, 256>>>(w3);
    expand_kernel<<<NBLK, 256>>>(feats, b1, s1);
    fused_kernel<<<NBLK, 288, SMEM_F>>>(nbr, w2, b2, b3, s2, s3, sm_, sr_, feats, out);
}

// round 4
// speedup vs baseline: 2.4244x; 1.1426x over previous
#include <cuda_runtime.h>
#include <cuda_fp16.h>
#include <cstdint>

#define NPTS 100000
#define CIN  96
#define CHID 576
#define COUT 96
#define TME  64           // expand tile
#define TM   32           // fused tile (100000 = 3125 * 32, no tail)
#define LDX  584          // x2s stride (halves): 1168B row -> ldmatrix conflict-free
#define FS   120          // feats tile stride (halves)
#define XS   104          // expand staging stride (halves)
#define NBLKE ((NPTS + TME - 1) / TME)   // 1563
#define NBLKF (NPTS / TM)                // 3125 exact

// ---------------- device scratch ----------------
__device__ __half g_x1[(size_t)NPTS * CHID];      // stage-1 activations (fp16, exact)
__device__ uint2  g_w1f[6  * 72 * 32];            // w1 B-fragments [ka][na][lane]
__device__ uint2  g_w3f[36 * 12 * 32];            // w3 B-fragments [ka][na][lane]

// ---------------- helpers ----------------
__device__ __forceinline__ void ldmatrix_x4(uint32_t* r, uint32_t saddr) {
    asm volatile("ldmatrix.sync.aligned.m8n8.x4.shared.b16 {%0,%1,%2,%3}, [%4];"
                 : "=r"(r[0]), "=r"(r[1]), "=r"(r[2]), "=r"(r[3]) : "r"(saddr));
}
__device__ __forceinline__ void mma16816(float* c, const uint32_t* a, const uint32_t* b) {
    asm volatile("mma.sync.aligned.m16n8k16.row.col.f32.f16.f16.f32 "
                 "{%0,%1,%2,%3}, {%4,%5,%6,%7}, {%8,%9}, {%0,%1,%2,%3};"
                 : "+f"(c[0]), "+f"(c[1]), "+f"(c[2]), "+f"(c[3])
                 : "r"(a[0]), "r"(a[1]), "r"(a[2]), "r"(a[3]), "r"(b[0]), "r"(b[1]));
}
__device__ __forceinline__ uint32_t pack2(float lo, float hi) {
    __half2 h = __floats2half2_rn(lo, hi);
    return *(uint32_t*)&h;
}
__device__ __forceinline__ unsigned long long pk64(float lo, float hi) {
    unsigned long long v;
    asm("mov.b64 %0, {%1, %2};" : "=l"(v) : "f"(lo), "f"(hi));
    return v;
}
__device__ __forceinline__ void upk64(float& lo, float& hi, unsigned long long v) {
    asm("mov.b64 {%0, %1}, %2;" : "=f"(lo), "=f"(hi) : "l"(v));
}
__device__ __forceinline__ void ffma2(unsigned long long& acc, unsigned long long a, unsigned long long b) {
    asm("fma.rn.f32x2 %0, %1, %2, %0;" : "+l"(acc) : "l"(a), "l"(b));
}
__device__ __forceinline__ unsigned long long fmul2(unsigned long long a, unsigned long long b) {
    unsigned long long o;
    asm("mul.rn.f32x2 %0, %1, %2;" : "=l"(o) : "l"(a), "l"(b));
    return o;
}
__device__ __forceinline__ unsigned long long h2tof2(uint32_t h) {
    float2 f = __half22float2(*(__half2*)&h);
    return pk64(f.x, f.y);
}

// ---------------- merged weight-fragment pack ----------------
__global__ void pack_wf(const float* __restrict__ w1, const float* __restrict__ w3) {
    int idx = blockIdx.x * blockDim.x + threadIdx.x;
    if (idx < 6 * 72 * 32) {
        int lane = idx & 31, na = (idx >> 5) % 72, ka = idx / (32 * 72);
        int k0 = ka * 16 + (lane & 3) * 2;
        int n  = na * 8 + (lane >> 2);
        uint2 v;
        v.x = pack2(w1[k0 * CHID + n],       w1[(k0 + 1) * CHID + n]);
        v.y = pack2(w1[(k0 + 8) * CHID + n], w1[(k0 + 9) * CHID + n]);
        g_w1f[idx] = v;
    } else {
        int j = idx - 6 * 72 * 32;
        if (j >= 36 * 12 * 32) return;
        int lane = j & 31, na = (j >> 5) % 12, ka = j / (32 * 12);
        int k0 = ka * 16 + (lane & 3) * 2;
        int n  = na * 8 + (lane >> 2);
        uint2 v;
        v.x = pack2(w3[k0 * COUT + n],       w3[(k0 + 1) * COUT + n]);
        v.y = pack2(w3[(k0 + 8) * COUT + n], w3[(k0 + 9) * COUT + n]);
        g_w3f[j] = v;
    }
}

// ---------------- stage 1: 1x1 expand (HMMA, bit-exact), single pass ----------------
__global__ __launch_bounds__(256) void expand_kernel(
    const float* __restrict__ feats,
    const float* __restrict__ b1, const float* __restrict__ s1) {
    __shared__ __align__(16) __half sfeat[TME * FS];
    __shared__ __align__(16) __half sxout[TME * XS];
    __shared__ float sb1[CHID], ss1[CHID];
    int t = threadIdx.x;
    int site0 = blockIdx.x * TME;

    #pragma unroll
    for (int it = 0; it < 12; it++) {
        int i = t + it * 256;
        int s = i / 48, c2 = i - s * 48;
        uint32_t v = 0;
        if (site0 + s < NPTS) {
            float2 f = *(const float2*)(feats + (size_t)(site0 + s) * CIN + 2 * c2);
            v = pack2(f.x, f.y);
        }
        *(uint32_t*)&sfeat[s * FS + 2 * c2] = v;
    }
    for (int i = t; i < CHID; i += 256) {
        sb1[i] = b1[i];
        ss1[i] = rintf(s1[i]) * (1.0f / 256.0f);
    }
    __syncthreads();

    int warp = t >> 5, lane = t & 31;
    int mbase = (warp & 1) * 32;
    int natom0 = (warp >> 1) * 3;
    uint32_t sbase = (uint32_t)__cvta_generic_to_shared(sfeat);

    uint32_t a[6][2][4];
    #pragma unroll
    for (int ka = 0; ka < 6; ka++)
        #pragma unroll
        for (int mi = 0; mi < 2; mi++) {
            int row = mbase + mi * 16 + (lane & 15);
            ldmatrix_x4(a[ka][mi], sbase + (row * FS + ka * 16 + (lane >> 4) * 8) * 2);
        }

    int r = lane >> 2, cl = (lane & 3) * 2;
    for (int c = 0; c < 6; c++) {
        float acc[2][3][4];
        #pragma unroll
        for (int mi = 0; mi < 2; mi++)
            #pragma unroll
            for (int ni = 0; ni < 3; ni++)
                #pragma unroll
                for (int j = 0; j < 4; j++) acc[mi][ni][j] = 0.0f;
        #pragma unroll
        for (int ka = 0; ka < 6; ka++) {
            uint2 b[3];
            #pragma unroll
            for (int ni = 0; ni < 3; ni++)
                b[ni] = g_w1f[(ka * 72 + c * 12 + natom0 + ni) * 32 + lane];
            #pragma unroll
            for (int mi = 0; mi < 2; mi++)
                #pragma unroll
                for (int ni = 0; ni < 3; ni++)
                    mma16816(acc[mi][ni], a[ka][mi], (const uint32_t*)&b[ni]);
        }
        #pragma unroll
        for (int ni = 0; ni < 3; ni++) {
            int chl = natom0 * 8 + ni * 8 + cl;
            int ch = c * 96 + chl;
            float rs0 = ss1[ch], rs1 = ss1[ch + 1];
            float bb0 = sb1[ch], bb1 = sb1[ch + 1];
            #pragma unroll
            for (int mi = 0; mi < 2; mi++)
                #pragma unroll
                for (int half = 0; half < 2; half++) {
                    int row = mbase + mi * 16 + r + half * 8;
                    float v0 = fminf(fmaxf((acc[mi][ni][half * 2 + 0] + bb0) * rs0, 0.0f), 6.0f);
                    float v1 = fminf(fmaxf((acc[mi][ni][half * 2 + 1] + bb1) * rs1, 0.0f), 6.0f);
                    *(uint32_t*)&sxout[row * XS + chl] = pack2(v0, v1);
                }
        }
        __syncthreads();
        #pragma unroll
        for (int it = 0; it < 3; it++) {
            int i = t + it * 256;
            int row = i / 12, q = i - row * 12;
            if (site0 + row < NPTS) {
                uint4 v = *(uint4*)&sxout[row * XS + q * 8];
                *(uint4*)&g_x1[(size_t)(site0 + row) * CHID + c * 96 + q * 8] = v;
            }
        }
        __syncthreads();
    }
}

// ---------------- stage 2+3: fused depthwise + project (HMMA) + residual ----------------
#define SMEM_F (TM * LDX * 2 + 9 * CHID * 4 + TM * 12 * 4)   // 59648 B

__global__ __launch_bounds__(288, 3) void fused_kernel(
    const int* __restrict__ nbr,
    const float* __restrict__ w2, const float* __restrict__ b2,
    const float* __restrict__ b3,
    const float* __restrict__ s2, const float* __restrict__ s3,
    const float* __restrict__ s_main, const float* __restrict__ s_res,
    const float* __restrict__ feats,
    float* __restrict__ out) {
    extern __shared__ __align__(16) char smraw[];
    __half* x2s   = (__half*)smraw;                 // [32][584]
    float*  sw2f  = (float*)(x2s + TM * LDX);       // [9][576] fp32
    int*    snbrp = (int*)(sw2f + 9 * CHID);        // [32][12] site-major

    int t = threadIdx.x;
    int site0 = blockIdx.x * TM;

    for (int i = t; i < 9 * CHID; i += 288) sw2f[i] = w2[i];
    for (int i = t; i < TM * 12; i += 288) {
        int k = i >> 5, s = i & 31;                 // coalesced over s per k
        snbrp[s * 12 + k] = (k < 9) ? nbr[k * NPTS + site0 + s] : -1;
    }
    __syncthreads();

    // ---- Phase A: depthwise 3x3 gather; thread = 4 channels x 16 sites ----
    {
        int g = t % 144, sh = t / 144;
        int cq = g * 4;
        const __half* x1cq = g_x1 + cq;
        float4 bq = *(const float4*)(b2 + cq);
        float4 sq = *(const float4*)(s2 + cq);
        unsigned long long b01 = pk64(bq.x, bq.y), b23 = pk64(bq.z, bq.w);
        unsigned long long r01 = pk64(rintf(sq.x) * (1.0f / 256.0f), rintf(sq.y) * (1.0f / 256.0f));
        unsigned long long r23 = pk64(rintf(sq.z) * (1.0f / 256.0f), rintf(sq.w) * (1.0f / 256.0f));
        const float* wg = sw2f + cq;

        #pragma unroll 2
        for (int s = 0; s < 16; s++) {
            int site = sh * 16 + s;
            int4 na = *(const int4*)&snbrp[site * 12];
            int4 nb = *(const int4*)&snbrp[site * 12 + 4];
            int  n8 = snbrp[site * 12 + 8];
            unsigned long long a01 = b01, a23 = b23;
            #define TAP(J, K) do { int _j = (J); if (_j >= 0) { \
                uint2 v = *(const uint2*)(x1cq + (size_t)_j * CHID); \
                float4 w = *(const float4*)(wg + (K) * CHID); \
                ffma2(a01, h2tof2(v.x), pk64(w.x, w.y)); \
                ffma2(a23, h2tof2(v.y), pk64(w.z, w.w)); } } while (0)
            TAP(na.x, 0); TAP(na.y, 1); TAP(na.z, 2); TAP(na.w, 3);
            TAP(nb.x, 4); TAP(nb.y, 5); TAP(nb.z, 6); TAP(nb.w, 7);
            TAP(n8, 8);
            #undef TAP
            a01 = fmul2(a01, r01);
            a23 = fmul2(a23, r23);
            float v0, v1, v2, v3;
            upk64(v0, v1, a01); upk64(v2, v3, a23);
            v0 = fminf(fmaxf(v0, 0.f), 6.f); v1 = fminf(fmaxf(v1, 0.f), 6.f);
            v2 = fminf(fmaxf(v2, 0.f), 6.f); v3 = fminf(fmaxf(v3, 0.f), 6.f);
            uint2 pr; pr.x = pack2(v0, v1); pr.y = pack2(v2, v3);
            *(uint2*)&x2s[site * LDX + cq] = pr;
        }
    }
    __syncthreads();

    // ---- Phase B: project GEMM [32x576]@[576x96] via HMMA (warps 0..7) ----
    int warp = t >> 5, lane = t & 31;
    if (warp < 8) {
        int mbase = (warp & 1) * 16;
        int natom0 = (warp >> 1) * 3;
        uint32_t sbase = (uint32_t)__cvta_generic_to_shared(x2s);

        float acc[3][4];
        #pragma unroll
        for (int ni = 0; ni < 3; ni++)
            #pragma unroll
            for (int j = 0; j < 4; j++) acc[ni][j] = 0.0f;

        #pragma unroll 3
        for (int ka = 0; ka < 36; ka++) {
            uint32_t a[4];
            ldmatrix_x4(a, sbase + ((mbase + (lane & 15)) * LDX + ka * 16 + (lane >> 4) * 8) * 2);
            uint2 b[3];
            #pragma unroll
            for (int ni = 0; ni < 3; ni++)
                b[ni] = g_w3f[(ka * 12 + natom0 + ni) * 32 + lane];
            #pragma unroll
            for (int ni = 0; ni < 3; ni++)
                mma16816(acc[ni], a, (const uint32_t*)&b[ni]);
        }

        float smain = rintf(s_main[0]) * 256.0f;
        float sres  = rintf(s_res[0]) * 256.0f;
        int r = lane >> 2, cl = (lane & 3) * 2;
        #pragma unroll
        for (int ni = 0; ni < 3; ni++) {
            int co = natom0 * 8 + ni * 8 + cl;
            float rs0 = rintf(s3[co]) * (1.0f / 256.0f);
            float rs1 = rintf(s3[co + 1]) * (1.0f / 256.0f);
            float bb0 = b3[co], bb1 = b3[co + 1];
            #pragma unroll
            for (int half = 0; half < 2; half++) {
                int site = site0 + mbase + r + half * 8;
                float v0 = (acc[ni][half * 2 + 0] + bb0) * rs0;
                float v1 = (acc[ni][half * 2 + 1] + bb1) * rs1;
                v0 = fminf(fmaxf(v0, -128.0f), 128.0f);
                v1 = fminf(fmaxf(v1, -128.0f), 128.0f);
                float2 fr = *(const float2*)(feats + (size_t)site * CIN + co);
                float2 o;
                o.x = smain * v0 + sres * fr.x;
                o.y = smain * v1 + sres * fr.y;
                *(float2*)(out + (size_t)site * COUT + co) = o;
            }
        }
    }
}

// ---------------- launch ----------------
extern "C" void kernel_launch(void* const* d_in, const int* in_sizes, int n_in,
                              void* d_out, int out_size) {
    const float* feats = (const float*)d_in[0];
    const int*   nbr   = (const int*)d_in[1];
    const float* w1    = (const float*)d_in[2];
    const float* b1    = (const float*)d_in[3];
    const float* w2    = (const float*)d_in[4];
    const float* b2    = (const float*)d_in[5];
    const float* w3    = (const float*)d_in[6];
    const float* b3    = (const float*)d_in[7];
    const float* s1    = (const float*)d_in[8];
    const float* s2    = (const float*)d_in[9];
    const float* s3    = (const float*)d_in[10];
    const float* sm_   = (const float*)d_in[11];
    const float* sr_   = (const float*)d_in[12];
    float* out = (float*)d_out;

    cudaFuncSetAttribute(fused_kernel, cudaFuncAttributeMaxDynamicSharedMemorySize, SMEM_F);

    pack_wf<<<(6 * 72 * 32 + 36 * 12 * 32 + 255) / 256, 256>>>(w1, w3);
    expand_kernel<<<NBLKE, 256>>>(feats, b1, s1);
    fused_kernel<<<NBLKF, 288, SMEM_F>>>(nbr, w2, b2, b3, s2, s3, sm_, sr_, feats, out);
}

// round 5
// speedup vs baseline: 2.7995x; 1.1547x over previous
#include <cuda_runtime.h>
#include <cuda_fp16.h>
#include <cstdint>

#define NPTS 100000
#define CIN  96
#define CHID 576
#define COUT 96
#define TME  64           // expand tile
#define TM   32           // fused tile (100000 = 3125 * 32, no tail)
#define LDX  584          // x2s stride (halves): 1168B row -> ldmatrix conflict-free
#define FS   120          // feats tile stride (halves)
#define XS   104          // expand staging stride (halves)
#define NBLKE ((NPTS + TME - 1) / TME)   // 1563
#define NBLKF (NPTS / TM)                // 3125 exact

// ---------------- device scratch ----------------
__device__ __half g_x1[(size_t)NPTS * CHID];      // stage-1 activations (fp16, exact)
__device__ uint2  g_w1f[6  * 72 * 32];            // w1 B-fragments [ka][na][lane]
__device__ uint2  g_w3f[36 * 12 * 32];            // w3 B-fragments [ka][na][lane]

// ---------------- helpers ----------------
__device__ __forceinline__ void ldmatrix_x4(uint32_t* r, uint32_t saddr) {
    asm volatile("ldmatrix.sync.aligned.m8n8.x4.shared.b16 {%0,%1,%2,%3}, [%4];"
                 : "=r"(r[0]), "=r"(r[1]), "=r"(r[2]), "=r"(r[3]) : "r"(saddr));
}
__device__ __forceinline__ void mma16816(float* c, const uint32_t* a, const uint32_t* b) {
    asm volatile("mma.sync.aligned.m16n8k16.row.col.f32.f16.f16.f32 "
                 "{%0,%1,%2,%3}, {%4,%5,%6,%7}, {%8,%9}, {%0,%1,%2,%3};"
                 : "+f"(c[0]), "+f"(c[1]), "+f"(c[2]), "+f"(c[3])
                 : "r"(a[0]), "r"(a[1]), "r"(a[2]), "r"(a[3]), "r"(b[0]), "r"(b[1]));
}
__device__ __forceinline__ uint32_t pack2(float lo, float hi) {
    __half2 h = __floats2half2_rn(lo, hi);
    return *(uint32_t*)&h;
}
__device__ __forceinline__ unsigned long long pk64(float lo, float hi) {
    unsigned long long v;
    asm("mov.b64 %0, {%1, %2};" : "=l"(v) : "f"(lo), "f"(hi));
    return v;
}
__device__ __forceinline__ void upk64(float& lo, float& hi, unsigned long long v) {
    asm("mov.b64 {%0, %1}, %2;" : "=f"(lo), "=f"(hi) : "l"(v));
}
__device__ __forceinline__ void ffma2(unsigned long long& acc, unsigned long long a, unsigned long long b) {
    asm("fma.rn.f32x2 %0, %1, %2, %0;" : "+l"(acc) : "l"(a), "l"(b));
}
__device__ __forceinline__ unsigned long long fmul2(unsigned long long a, unsigned long long b) {
    unsigned long long o;
    asm("mul.rn.f32x2 %0, %1, %2;" : "=l"(o) : "l"(a), "l"(b));
    return o;
}
__device__ __forceinline__ unsigned long long h2tof2(uint32_t h) {
    float2 f = __half22float2(*(__half2*)&h);
    return pk64(f.x, f.y);
}

// ---------------- merged weight-fragment pack ----------------
__global__ void pack_wf(const float* __restrict__ w1, const float* __restrict__ w3) {
    int idx = blockIdx.x * blockDim.x + threadIdx.x;
    if (idx < 6 * 72 * 32) {
        int lane = idx & 31, na = (idx >> 5) % 72, ka = idx / (32 * 72);
        int k0 = ka * 16 + (lane & 3) * 2;
        int n  = na * 8 + (lane >> 2);
        uint2 v;
        v.x = pack2(w1[k0 * CHID + n],       w1[(k0 + 1) * CHID + n]);
        v.y = pack2(w1[(k0 + 8) * CHID + n], w1[(k0 + 9) * CHID + n]);
        g_w1f[idx] = v;
    } else {
        int j = idx - 6 * 72 * 32;
        if (j >= 36 * 12 * 32) return;
        int lane = j & 31, na = (j >> 5) % 12, ka = j / (32 * 12);
        int k0 = ka * 16 + (lane & 3) * 2;
        int n  = na * 8 + (lane >> 2);
        uint2 v;
        v.x = pack2(w3[k0 * COUT + n],       w3[(k0 + 1) * COUT + n]);
        v.y = pack2(w3[(k0 + 8) * COUT + n], w3[(k0 + 9) * COUT + n]);
        g_w3f[j] = v;
    }
}

// ---------------- stage 1: 1x1 expand (HMMA, bit-exact) ----------------
__global__ __launch_bounds__(256, 3) void expand_kernel(
    const float* __restrict__ feats,
    const float* __restrict__ b1, const float* __restrict__ s1) {
    __shared__ __align__(16) __half sfeat[TME * FS];
    __shared__ __align__(16) __half sxout[TME * XS];
    __shared__ float sb1[CHID], ss1[CHID];
    int t = threadIdx.x;
    int site0 = blockIdx.x * TME;

    #pragma unroll
    for (int it = 0; it < 12; it++) {
        int i = t + it * 256;
        int s = i / 48, c2 = i - s * 48;
        uint32_t v = 0;
        if (site0 + s < NPTS) {
            float2 f = *(const float2*)(feats + (size_t)(site0 + s) * CIN + 2 * c2);
            v = pack2(f.x, f.y);
        }
        *(uint32_t*)&sfeat[s * FS + 2 * c2] = v;
    }
    for (int i = t; i < CHID; i += 256) {
        sb1[i] = b1[i];
        ss1[i] = rintf(s1[i]) * (1.0f / 256.0f);
    }
    __syncthreads();

    int warp = t >> 5, lane = t & 31;
    int mbase = (warp & 1) * 32;
    int natom0 = (warp >> 1) * 3;
    uint32_t sbase = (uint32_t)__cvta_generic_to_shared(sfeat);
    int r = lane >> 2, cl = (lane & 3) * 2;

    for (int c = 0; c < 6; c++) {
        float acc[2][3][4];
        #pragma unroll
        for (int mi = 0; mi < 2; mi++)
            #pragma unroll
            for (int ni = 0; ni < 3; ni++)
                #pragma unroll
                for (int j = 0; j < 4; j++) acc[mi][ni][j] = 0.0f;
        #pragma unroll
        for (int ka = 0; ka < 6; ka++) {
            uint32_t a[2][4];
            #pragma unroll
            for (int mi = 0; mi < 2; mi++) {
                int row = mbase + mi * 16 + (lane & 15);
                ldmatrix_x4(a[mi], sbase + (row * FS + ka * 16 + (lane >> 4) * 8) * 2);
            }
            uint2 b[3];
            #pragma unroll
            for (int ni = 0; ni < 3; ni++)
                b[ni] = g_w1f[(ka * 72 + c * 12 + natom0 + ni) * 32 + lane];
            #pragma unroll
            for (int mi = 0; mi < 2; mi++)
                #pragma unroll
                for (int ni = 0; ni < 3; ni++)
                    mma16816(acc[mi][ni], a[mi], (const uint32_t*)&b[ni]);
        }
        #pragma unroll
        for (int ni = 0; ni < 3; ni++) {
            int chl = natom0 * 8 + ni * 8 + cl;
            int ch = c * 96 + chl;
            float rs0 = ss1[ch], rs1 = ss1[ch + 1];
            float bb0 = sb1[ch], bb1 = sb1[ch + 1];
            #pragma unroll
            for (int mi = 0; mi < 2; mi++)
                #pragma unroll
                for (int half = 0; half < 2; half++) {
                    int row = mbase + mi * 16 + r + half * 8;
                    float v0 = fminf(fmaxf((acc[mi][ni][half * 2 + 0] + bb0) * rs0, 0.0f), 6.0f);
                    float v1 = fminf(fmaxf((acc[mi][ni][half * 2 + 1] + bb1) * rs1, 0.0f), 6.0f);
                    *(uint32_t*)&sxout[row * XS + chl] = pack2(v0, v1);
                }
        }
        __syncthreads();
        #pragma unroll
        for (int it = 0; it < 3; it++) {
            int i = t + it * 256;
            int row = i / 12, q = i - row * 12;
            if (site0 + row < NPTS) {
                uint4 v = *(uint4*)&sxout[row * XS + q * 8];
                *(uint4*)&g_x1[(size_t)(site0 + row) * CHID + c * 96 + q * 8] = v;
            }
        }
        __syncthreads();
    }
}

// ---------------- stage 2+3: fused depthwise + project (HMMA) + residual ----------------
// smem: x2s 37376 + sw2f(8 taps) 18432 + snbr(8 taps) 1024 = 56832 B -> 4 CTAs/SM
#define SMEM_F (TM * LDX * 2 + 8 * CHID * 4 + TM * 8 * 4)

__global__ __launch_bounds__(288, 4) void fused_kernel(
    const int* __restrict__ nbr,
    const float* __restrict__ w2, const float* __restrict__ b2,
    const float* __restrict__ b3,
    const float* __restrict__ s2, const float* __restrict__ s3,
    const float* __restrict__ s_main, const float* __restrict__ s_res,
    const float* __restrict__ feats,
    float* __restrict__ out) {
    extern __shared__ __align__(16) char smraw[];
    __half* x2s   = (__half*)smraw;                 // [32][584]
    float*  sw2f  = (float*)(x2s + TM * LDX);       // [8][576] fp32 (taps 0-3,5-8)
    int*    snbrp = (int*)(sw2f + 8 * CHID);        // [32][8] site-major (non-center taps)

    int t = threadIdx.x;
    int site0 = blockIdx.x * TM;

    for (int i = t; i < 8 * CHID; i += 288) {
        int rr = i / CHID, c = i - rr * CHID;
        sw2f[i] = w2[(rr + (rr >= 4)) * CHID + c];
    }
    if (t < TM * 8) {
        int k8 = t >> 5, s = t & 31;                // coalesced over s per tap
        snbrp[s * 8 + k8] = nbr[(k8 + (k8 >= 4)) * NPTS + site0 + s];
    }
    __syncthreads();

    // ---- Phase A: depthwise 3x3 gather; thread = 4 channels x 16 sites ----
    {
        int g = t % 144, sh = t / 144;
        int cq = g * 4;
        const __half* x1cq = g_x1 + cq;
        float4 bq = *(const float4*)(b2 + cq);
        float4 sq = *(const float4*)(s2 + cq);
        float4 wc = *(const float4*)(w2 + 4 * CHID + cq);   // center-tap weights (regs)
        unsigned long long wc01 = pk64(wc.x, wc.y), wc23 = pk64(wc.z, wc.w);
        unsigned long long b01 = pk64(bq.x, bq.y), b23 = pk64(bq.z, bq.w);
        unsigned long long r01 = pk64(rintf(sq.x) * (1.0f / 256.0f), rintf(sq.y) * (1.0f / 256.0f));
        unsigned long long r23 = pk64(rintf(sq.z) * (1.0f / 256.0f), rintf(sq.w) * (1.0f / 256.0f));
        const float* wg = sw2f + cq;

        #pragma unroll 2
        for (int s = 0; s < 16; s++) {
            int site = sh * 16 + s;
            int4 na = *(const int4*)&snbrp[site * 8];
            int4 nb = *(const int4*)&snbrp[site * 8 + 4];
            // center tap: always valid, index = site0 + site (no branch)
            uint2 vc = *(const uint2*)(x1cq + (size_t)(site0 + site) * CHID);
            unsigned long long a01 = b01, a23 = b23;
            ffma2(a01, h2tof2(vc.x), wc01);
            ffma2(a23, h2tof2(vc.y), wc23);
            #define TAP(J, K) do { int _j = (J); if (_j >= 0) { \
                uint2 v = *(const uint2*)(x1cq + (size_t)_j * CHID); \
                float4 w = *(const float4*)(wg + (K) * CHID); \
                ffma2(a01, h2tof2(v.x), pk64(w.x, w.y)); \
                ffma2(a23, h2tof2(v.y), pk64(w.z, w.w)); } } while (0)
            TAP(na.x, 0); TAP(na.y, 1); TAP(na.z, 2); TAP(na.w, 3);
            TAP(nb.x, 4); TAP(nb.y, 5); TAP(nb.z, 6); TAP(nb.w, 7);
            #undef TAP
            a01 = fmul2(a01, r01);
            a23 = fmul2(a23, r23);
            float v0, v1, v2, v3;
            upk64(v0, v1, a01); upk64(v2, v3, a23);
            v0 = fminf(fmaxf(v0, 0.f), 6.f); v1 = fminf(fmaxf(v1, 0.f), 6.f);
            v2 = fminf(fmaxf(v2, 0.f), 6.f); v3 = fminf(fmaxf(v3, 0.f), 6.f);
            uint2 pr; pr.x = pack2(v0, v1); pr.y = pack2(v2, v3);
            *(uint2*)&x2s[site * LDX + cq] = pr;
        }
    }
    __syncthreads();

    // ---- Phase B: project GEMM [32x576]@[576x96] via HMMA (warps 0..7) ----
    int warp = t >> 5, lane = t & 31;
    if (warp < 8) {
        int mbase = (warp & 1) * 16;
        int natom0 = (warp >> 1) * 3;
        uint32_t sbase = (uint32_t)__cvta_generic_to_shared(x2s);

        float acc[3][4];
        #pragma unroll
        for (int ni = 0; ni < 3; ni++)
            #pragma unroll
            for (int j = 0; j < 4; j++) acc[ni][j] = 0.0f;

        #pragma unroll 3
        for (int ka = 0; ka < 36; ka++) {
            uint32_t a[4];
            ldmatrix_x4(a, sbase + ((mbase + (lane & 15)) * LDX + ka * 16 + (lane >> 4) * 8) * 2);
            uint2 b[3];
            #pragma unroll
            for (int ni = 0; ni < 3; ni++)
                b[ni] = g_w3f[(ka * 12 + natom0 + ni) * 32 + lane];
            #pragma unroll
            for (int ni = 0; ni < 3; ni++)
                mma16816(acc[ni], a, (const uint32_t*)&b[ni]);
        }

        float smain = rintf(s_main[0]) * 256.0f;
        float sres  = rintf(s_res[0]) * 256.0f;
        int r = lane >> 2, cl = (lane & 3) * 2;
        #pragma unroll
        for (int ni = 0; ni < 3; ni++) {
            int co = natom0 * 8 + ni * 8 + cl;
            float rs0 = rintf(s3[co]) * (1.0f / 256.0f);
            float rs1 = rintf(s3[co + 1]) * (1.0f / 256.0f);
            float bb0 = b3[co], bb1 = b3[co + 1];
            #pragma unroll
            for (int half = 0; half < 2; half++) {
                int site = site0 + mbase + r + half * 8;
                float v0 = (acc[ni][half * 2 + 0] + bb0) * rs0;
                float v1 = (acc[ni][half * 2 + 1] + bb1) * rs1;
                v0 = fminf(fmaxf(v0, -128.0f), 128.0f);
                v1 = fminf(fmaxf(v1, -128.0f), 128.0f);
                float2 fr = *(const float2*)(feats + (size_t)site * CIN + co);
                float2 o;
                o.x = smain * v0 + sres * fr.x;
                o.y = smain * v1 + sres * fr.y;
                *(float2*)(out + (size_t)site * COUT + co) = o;
            }
        }
    }
}

// ---------------- launch ----------------
extern "C" void kernel_launch(void* const* d_in, const int* in_sizes, int n_in,
                              void* d_out, int out_size) {
    const float* feats = (const float*)d_in[0];
    const int*   nbr   = (const int*)d_in[1];
    const float* w1    = (const float*)d_in[2];
    const float* b1    = (const float*)d_in[3];
    const float* w2    = (const float*)d_in[4];
    const float* b2    = (const float*)d_in[5];
    const float* w3    = (const float*)d_in[6];
    const float* b3    = (const float*)d_in[7];
    const float* s1    = (const float*)d_in[8];
    const float* s2    = (const float*)d_in[9];
    const float* s3    = (const float*)d_in[10];
    const float* sm_   = (const float*)d_in[11];
    const float* sr_   = (const float*)d_in[12];
    float* out = (float*)d_out;

    cudaFuncSetAttribute(fused_kernel, cudaFuncAttributeMaxDynamicSharedMemorySize, SMEM_F);

    pack_wf<<<(6 * 72 * 32 + 36 * 12 * 32 + 255) / 256, 256>>>(w1, w3);
    expand_kernel<<<NBLKE, 256>>>(feats, b1, s1);
    fused_kernel<<<NBLKF, 288, SMEM_F>>>(nbr, w2, b2, b3, s2, s3, sm_, sr_, feats, out);
}